// round 5
// baseline (speedup 1.0000x reference)
#include <cuda_runtime.h>
#include <cuda_fp16.h>
#include <math.h>
#include <stdint.h>

// ---------------- problem constants ----------------
#define BATCH 2048
#define DIMD  1024
#define UNITS 1024
#define MEMS  8
#define SLOTS 9                 // M + 1
#define ROWS  (BATCH*SLOTS)     // 18432
#define HEADS 16
#define DH    64
#define GROWS (BATCH*MEMS)      // 16384
#define LN_EPS 1e-5f

// ---------------- scratch (device globals) ----------------
__device__ __align__(16) __half g_memplus[ROWS*UNITS];   // [B,9,U] fp16
__device__ __align__(16) __half g_qkv[ROWS*3*UNITS];     // fp16
__device__ __align__(16) __half g_h[ROWS*UNITS];         // LN1 out fp16
__device__ __align__(16) __half g_t[ROWS*UNITS];         // gelu out fp16
__device__ __align__(16) __half g_xr[BATCH*DIMD];        // inputs fp16
__device__ float g_att[ROWS*UNITS];
__device__ float g_hm[ROWS*UNITS];
__device__ float g_h2[ROWS*UNITS];
__device__ float g_g0[BATCH*2*UNITS];                    // interleaved i/f
__device__ float g_tab[17*UNITS];
__device__ float g_rel[17*UNITS];
// transposed [N,K] fp16 weights
__device__ __align__(16) __half wt_ingate[3*UNITS*DIMD]; // rows 0-1023 Wi^T, 1024-3071 Wgate^T (interleaved)
__device__ __align__(16) __half wt_rec[2*UNITS*UNITS];   // interleaved i/f rows
__device__ __align__(16) __half wt_att[3*UNITS*UNITS];
__device__ __align__(16) __half wt_mlp[2*UNITS*UNITS];

// ---------------- helpers ----------------
__device__ __forceinline__ float gelu_tanh(float x) {
    const float c0 = 0.7978845608028654f;
    const float c1 = 0.044715f;
    return 0.5f * x * (1.0f + tanhf(c0 * (x + c1 * x * x * x)));
}
__device__ __forceinline__ float hsig(float x) { return __saturatef(0.2f * x + 0.5f); }
__device__ __forceinline__ unsigned smem_u32(const void* p) {
    return (unsigned)__cvta_generic_to_shared(p);
}

// ============================================================================
// FP16 tensor-core GEMM (mma.sync.m16n8k16) with fused epilogues.
// C[M,N] = A[M,K] @ Bt[N,K]^T ; CTA tile 128x256x64, 512 thr, 4-stage cp.async
// ============================================================================
#define BM 128
#define BN 256
#define BK 64
#define ROWB 144
#define A_BYTES (BM*ROWB)
#define B_BYTES (BN*ROWB)
#define STG (A_BYTES + B_BYTES)
#define NST 4
#define HG_SMEM (NST*STG)

#define EPI_BIAS_H 0   // bias, fp16 out
#define EPI_GELU   1   // bias, gelu, fp16 out
#define EPI_RES    2   // bias + fp16 residual, fp32 out
#define EPI_INGATE 3   // cols<1024: bias+fp16 -> memplus slot8 ; cols>=1024: fp32 -> g0
#define EPI_GATES  4   // full gate math -> out (fp32)

template<int EPI, bool REMAP>
__global__ void __launch_bounds__(512, 1)
hgemm(const __half* __restrict__ A, int lda,
      const __half* __restrict__ Bt, int ldb,
      const float* __restrict__ bias,
      const __half* __restrict__ resh, int ldres,
      const float* __restrict__ pf1,     // EPI_GATES: g0
      const float* __restrict__ pf2,     // EPI_GATES: state
      const float* __restrict__ pf3,     // EPI_GATES: h2   EPI_INGATE: g0 out (cast)
      void* __restrict__ Cv, int ldc,
      int M, int N, int K)
{
    extern __shared__ char sm[];
    const unsigned smb = smem_u32(sm);
    const int tid  = threadIdx.x;
    const int lane = tid & 31;
    const int wid  = tid >> 5;
    const int bm0 = blockIdx.y * BM;
    const int bn0 = blockIdx.x * BN;
    const int wm = (wid & 3) * 32;
    const int wn = (wid >> 2) * 64;

    const unsigned aoff = (unsigned)(((lane & 7) + ((lane >> 3) & 1) * 8) * ROWB
                                     + (lane >> 4) * 16);
    const unsigned boff = (unsigned)(((lane & 7) + (lane >> 4) * 8) * ROWB
                                     + ((lane >> 3) & 1) * 16);

    const int lrow = tid >> 3;
    const int lchk = tid & 7;
    auto load_stage = [&](int s, int kt) {
        const int k0 = kt * BK;
        const unsigned abase = smb + s * STG;
        #pragma unroll
        for (int i = 0; i < 2; i++) {
            const int r = lrow + 64 * i;
            const int gr = bm0 + r;
            const int arow = REMAP ? gr + (gr >> 3) : gr;
            const unsigned d = abase + (unsigned)(r * ROWB + lchk * 16);
            const __half* g = A + (size_t)arow * lda + k0 + lchk * 8;
            asm volatile("cp.async.cg.shared.global [%0], [%1], 16;" :: "r"(d), "l"(g));
        }
        const unsigned bbase = abase + A_BYTES;
        #pragma unroll
        for (int i = 0; i < 4; i++) {
            const int r = lrow + 64 * i;
            const unsigned d = bbase + (unsigned)(r * ROWB + lchk * 16);
            const __half* g = Bt + (size_t)(bn0 + r) * ldb + k0 + lchk * 8;
            asm volatile("cp.async.cg.shared.global [%0], [%1], 16;" :: "r"(d), "l"(g));
        }
    };

    float acc[2][8][4];
    #pragma unroll
    for (int mt = 0; mt < 2; mt++)
        #pragma unroll
        for (int nt = 0; nt < 8; nt++)
            #pragma unroll
            for (int r = 0; r < 4; r++) acc[mt][nt][r] = 0.0f;

    const int kiters = K / BK;
    load_stage(0, 0); asm volatile("cp.async.commit_group;" ::: "memory");
    load_stage(1, 1); asm volatile("cp.async.commit_group;" ::: "memory");
    load_stage(2, 2); asm volatile("cp.async.commit_group;" ::: "memory");

    for (int kt = 0; kt < kiters; kt++) {
        const int s = kt & 3;
        asm volatile("cp.async.wait_group 2;" ::: "memory");
        __syncthreads();

        const unsigned abase = smb + s * STG + (unsigned)(wm * ROWB) + aoff;
        const unsigned bbase = smb + s * STG + A_BYTES + (unsigned)(wn * ROWB) + boff;

        #pragma unroll
        for (int k16 = 0; k16 < 4; k16++) {
            uint32_t af[2][4];
            #pragma unroll
            for (int mt = 0; mt < 2; mt++) {
                const unsigned addr = abase + (unsigned)(mt * 16 * ROWB + k16 * 32);
                asm volatile("ldmatrix.sync.aligned.m8n8.x4.shared.b16 {%0,%1,%2,%3}, [%4];"
                             : "=r"(af[mt][0]), "=r"(af[mt][1]),
                               "=r"(af[mt][2]), "=r"(af[mt][3]) : "r"(addr));
            }
            uint32_t bf[4][4];
            #pragma unroll
            for (int np = 0; np < 4; np++) {
                const unsigned addr = bbase + (unsigned)(np * 16 * ROWB + k16 * 32);
                asm volatile("ldmatrix.sync.aligned.m8n8.x4.shared.b16 {%0,%1,%2,%3}, [%4];"
                             : "=r"(bf[np][0]), "=r"(bf[np][1]),
                               "=r"(bf[np][2]), "=r"(bf[np][3]) : "r"(addr));
            }
            #pragma unroll
            for (int mt = 0; mt < 2; mt++)
                #pragma unroll
                for (int np = 0; np < 4; np++) {
                    asm volatile(
                        "mma.sync.aligned.m16n8k16.row.col.f32.f16.f16.f32 "
                        "{%0,%1,%2,%3}, {%4,%5,%6,%7}, {%8,%9}, {%0,%1,%2,%3};"
                        : "+f"(acc[mt][2*np][0]), "+f"(acc[mt][2*np][1]),
                          "+f"(acc[mt][2*np][2]), "+f"(acc[mt][2*np][3])
                        : "r"(af[mt][0]), "r"(af[mt][1]), "r"(af[mt][2]), "r"(af[mt][3]),
                          "r"(bf[np][0]), "r"(bf[np][1]));
                    asm volatile(
                        "mma.sync.aligned.m16n8k16.row.col.f32.f16.f16.f32 "
                        "{%0,%1,%2,%3}, {%4,%5,%6,%7}, {%8,%9}, {%0,%1,%2,%3};"
                        : "+f"(acc[mt][2*np+1][0]), "+f"(acc[mt][2*np+1][1]),
                          "+f"(acc[mt][2*np+1][2]), "+f"(acc[mt][2*np+1][3])
                        : "r"(af[mt][0]), "r"(af[mt][1]), "r"(af[mt][2]), "r"(af[mt][3]),
                          "r"(bf[np][2]), "r"(bf[np][3]));
                }
        }

        if (kt + 3 < kiters) load_stage((kt + 3) & 3, kt + 3);
        asm volatile("cp.async.commit_group;" ::: "memory");
    }

    // --- epilogue ---
    #pragma unroll
    for (int mt = 0; mt < 2; mt++) {
        const int r0 = bm0 + wm + mt * 16 + (lane >> 2);
        const int r1 = r0 + 8;
        #pragma unroll
        for (int nt = 0; nt < 8; nt++) {
            const int c = bn0 + wn + nt * 8 + ((lane & 3) << 1);
            float2 v0 = make_float2(acc[mt][nt][0], acc[mt][nt][1]);
            float2 v1 = make_float2(acc[mt][nt][2], acc[mt][nt][3]);

            if (EPI == EPI_GATES) {
                const int j = c >> 1;
                const float bi = __ldg(bias + j);
                const float bfv = __ldg(bias + 1024 + j);
                // row r0
                {
                    const int gr = r0, b = gr >> 3;
                    const float2 g0v = *(const float2*)(pf1 + (size_t)b * 2048 + c);
                    const float i_g = hsig(v0.x + g0v.x + bi);
                    const float f_g = hsig(v0.y + g0v.y + bfv + 1.0f);
                    const float mem = pf2[(size_t)gr * UNITS + j];
                    const float nm  = pf3[(size_t)(gr + (gr >> 3)) * UNITS + j];
                    ((float*)Cv)[(size_t)gr * UNITS + j] = f_g * mem + i_g * tanhf(nm);
                }
                // row r1
                {
                    const int gr = r1, b = gr >> 3;
                    const float2 g0v = *(const float2*)(pf1 + (size_t)b * 2048 + c);
                    const float i_g = hsig(v1.x + g0v.x + bi);
                    const float f_g = hsig(v1.y + g0v.y + bfv + 1.0f);
                    const float mem = pf2[(size_t)gr * UNITS + j];
                    const float nm  = pf3[(size_t)(gr + (gr >> 3)) * UNITS + j];
                    ((float*)Cv)[(size_t)gr * UNITS + j] = f_g * mem + i_g * tanhf(nm);
                }
                continue;
            }

            if (EPI == EPI_INGATE) {
                if (c < 1024) {
                    const float bx = bias[c], by = bias[c + 1];
                    v0.x += bx; v0.y += by; v1.x += bx; v1.y += by;
                    __half* C = (__half*)Cv;
                    *(__half2*)(C + (size_t)r0 * ldc + c) = __floats2half2_rn(v0.x, v0.y);
                    *(__half2*)(C + (size_t)r1 * ldc + c) = __floats2half2_rn(v1.x, v1.y);
                } else {
                    float* G = (float*)pf3;
                    *(float2*)(G + (size_t)r0 * 2048 + (c - 1024)) = v0;
                    *(float2*)(G + (size_t)r1 * 2048 + (c - 1024)) = v1;
                }
                continue;
            }

            // bias-based epilogues
            {
                const float bx = bias[c], by = bias[c + 1];
                v0.x += bx; v0.y += by; v1.x += bx; v1.y += by;
            }
            if (EPI == EPI_GELU) {
                v0.x = gelu_tanh(v0.x); v0.y = gelu_tanh(v0.y);
                v1.x = gelu_tanh(v1.x); v1.y = gelu_tanh(v1.y);
            }
            if (EPI == EPI_RES) {
                const __half2 ra = *(const __half2*)(resh + (size_t)r0 * ldres + c);
                const __half2 rb = *(const __half2*)(resh + (size_t)r1 * ldres + c);
                const float2 fa = __half22float2(ra), fb = __half22float2(rb);
                v0.x += fa.x; v0.y += fa.y; v1.x += fb.x; v1.y += fb.y;
                float* C = (float*)Cv;
                *(float2*)(C + (size_t)r0 * ldc + c) = v0;
                *(float2*)(C + (size_t)r1 * ldc + c) = v1;
            } else {
                __half* C = (__half*)Cv;
                *(__half2*)(C + (size_t)r0 * ldc + c) = __floats2half2_rn(v0.x, v0.y);
                *(__half2*)(C + (size_t)r1 * ldc + c) = __floats2half2_rn(v1.x, v1.y);
            }
        }
    }
}

// ---------------- small kernels --------------------------------------------

__global__ void to_half_kernel(const float* __restrict__ src, __half* __restrict__ dst, int n4) {
    const int i = blockIdx.x * blockDim.x + threadIdx.x;
    if (i < n4) {
        const float4 v = ((const float4*)src)[i];
        ((__half2*)dst)[2*i]   = __floats2half2_rn(v.x, v.y);
        ((__half2*)dst)[2*i+1] = __floats2half2_rn(v.z, v.w);
    }
}

// one launch: transpose+convert all 5 weight matrices [K=1024, N] -> [N,1024] fp16
// n-tile boundaries (32-col tiles): in 32 | gate 64 | rec 64 | att 96 | mlp 64
__global__ void transpose_all_kernel(
    const float* __restrict__ w_in, const float* __restrict__ w_gate,
    const float* __restrict__ w_rec, const float* __restrict__ w_att,
    const float* __restrict__ w_mlp)
{
    __shared__ float t[32][33];
    const int tx = threadIdx.x, ty = threadIdx.y;     // 32 x 8
    const int bx = blockIdx.x;
    const int k0 = blockIdx.y * 32;

    const float* src; __half* dst; int N; int ntile; int mode; // mode: 0 plain, 1 interleave
    int drow_base = 0;
    if (bx < 32)        { src = w_in;   dst = wt_ingate; N = 1024; ntile = bx;       mode = 0; }
    else if (bx < 96)   { src = w_gate; dst = wt_ingate; N = 2048; ntile = bx - 32;  mode = 1; drow_base = 1024; }
    else if (bx < 160)  { src = w_rec;  dst = wt_rec;    N = 2048; ntile = bx - 96;  mode = 1; }
    else if (bx < 256)  { src = w_att;  dst = wt_att;    N = 3072; ntile = bx - 160; mode = 0; }
    else                { src = w_mlp;  dst = wt_mlp;    N = 2048; ntile = bx - 256; mode = 0; }
    const int n0 = ntile * 32;

    #pragma unroll
    for (int i = 0; i < 32; i += 8)
        t[ty + i][tx] = src[(size_t)(k0 + ty + i) * N + n0 + tx];
    __syncthreads();
    #pragma unroll
    for (int i = 0; i < 32; i += 8) {
        const int n = n0 + ty + i;
        const int drow = drow_base + (mode ? ((n < 1024) ? 2*n : 2*(n-1024)+1) : n);
        dst[(size_t)drow * 1024 + k0 + tx] = __float2half_rn(t[tx][ty + i]);
    }
}

// state [B,8*U] -> memplus slots 0..7 (fp16)
__global__ void copy_state_kernel(const float* __restrict__ state) {
    const int row = blockIdx.x;
    const int b = row >> 3, m = row & 7;
    const int tid = threadIdx.x;
    const float4 v = ((const float4*)(state + (size_t)row * UNITS))[tid];
    __half2* d0 = (__half2*)(g_memplus + ((size_t)b * SLOTS + m) * UNITS);
    d0[2*tid]   = __floats2half2_rn(v.x, v.y);
    d0[2*tid+1] = __floats2half2_rn(v.z, v.w);
}

__global__ void tab_kernel() {
    const int p = blockIdx.x;
    const float pos = (float)(p - MEMS);
    for (int j = threadIdx.x; j < UNITS; j += blockDim.x) {
        const float expo = (float)(j - (j & 1)) / (float)UNITS;
        const float angle = pos * __expf(-expo * 9.210340371976184f);
        g_tab[p * UNITS + j] = (j & 1) ? cosf(angle) : sinf(angle);
    }
}

__global__ void relgemm_kernel(const float* __restrict__ rel_kernel) {
    const int p = blockIdx.y;
    const int n = blockIdx.x * blockDim.x + threadIdx.x;
    float acc = 0.0f;
    const float* tp = g_tab + p * UNITS;
    for (int j = 0; j < UNITS; j++)
        acc = fmaf(tp[j], rel_kernel[(size_t)j * UNITS + n], acc);
    g_rel[p * UNITS + n] = acc;
}

// attention per (b, h): S=9, dh=64; qkv fp16, compute fp32, att fp32
__global__ void __launch_bounds__(64) attn_kernel() {
    const int b = blockIdx.x, h = blockIdx.y;
    const int tid = threadIdx.x;

    __shared__ float q[SLOTS][DH], k[SLOTS][DH], v[SLOTS][DH];
    __shared__ float r[17][DH];
    __shared__ float sc[SLOTS * SLOTS];

    const float scale = 0.125f;
    const size_t base = ((size_t)b * SLOTS) * (3 * UNITS) + (size_t)h * DH;

    for (int i = tid; i < SLOTS * DH; i += 64) {
        const int s = i >> 6, d = i & 63;
        const size_t o = base + (size_t)s * (3 * UNITS) + d;
        q[s][d] = __half2float(g_qkv[o]) * scale;
        k[s][d] = __half2float(g_qkv[o + UNITS]);
        v[s][d] = __half2float(g_qkv[o + 2 * UNITS]);
    }
    for (int i = tid; i < 17 * DH; i += 64) {
        const int p = i >> 6, d = i & 63;
        r[p][d] = g_rel[p * UNITS + h * DH + d];
    }
    __syncthreads();

    for (int p = tid; p < SLOTS * SLOTS; p += 64) {
        const int qi = p / SLOTS, ki = p % SLOTS;
        const float* rr = r[qi - ki + MEMS];
        float acc = 0.0f;
        #pragma unroll 16
        for (int d = 0; d < DH; d++)
            acc = fmaf(q[qi][d], k[ki][d] + rr[d], acc);
        sc[p] = acc;
    }
    __syncthreads();

    if (tid < SLOTS) {
        float mx = -1e30f;
        #pragma unroll
        for (int j = 0; j < SLOTS; j++) mx = fmaxf(mx, sc[tid * SLOTS + j]);
        float e[SLOTS], sum = 0.0f;
        #pragma unroll
        for (int j = 0; j < SLOTS; j++) { e[j] = __expf(sc[tid * SLOTS + j] - mx); sum += e[j]; }
        const float inv = 1.0f / sum;
        #pragma unroll
        for (int j = 0; j < SLOTS; j++) sc[tid * SLOTS + j] = e[j] * inv;
    }
    __syncthreads();

    const int d = tid;
    #pragma unroll
    for (int qi = 0; qi < SLOTS; qi++) {
        float acc = 0.0f;
        #pragma unroll
        for (int kk = 0; kk < SLOTS; kk++)
            acc = fmaf(sc[qi * SLOTS + kk], v[kk][d], acc);
        g_att[((size_t)b * SLOTS + qi) * UNITS + h * DH + d] = acc;
    }
}

// LN1: h = LN(memplus_fp16 + att_fp32) -> fp16
__global__ void __launch_bounds__(256)
ln1_kernel(const float* __restrict__ gamma, const float* __restrict__ beta)
{
    const int row = blockIdx.x;
    const int tid = threadIdx.x;
    const __half2* xh = (const __half2*)(g_memplus + (size_t)row * UNITS);
    const float2 a0 = __half22float2(xh[2*tid]);
    const float2 a1 = __half22float2(xh[2*tid+1]);
    const float4 y = ((const float4*)(g_att + (size_t)row * UNITS))[tid];
    float4 x = make_float4(a0.x + y.x, a0.y + y.y, a1.x + y.z, a1.y + y.w);

    float s  = x.x + x.y + x.z + x.w;
    float ss = x.x*x.x + x.y*x.y + x.z*x.z + x.w*x.w;
    __shared__ float red[16];
    #pragma unroll
    for (int o = 16; o > 0; o >>= 1) {
        s  += __shfl_down_sync(0xffffffff, s, o);
        ss += __shfl_down_sync(0xffffffff, ss, o);
    }
    const int warp = tid >> 5, lane = tid & 31;
    if (lane == 0) { red[warp] = s; red[warp + 8] = ss; }
    __syncthreads();
    if (tid == 0) {
        float ts = 0.0f, tss = 0.0f;
        #pragma unroll
        for (int w = 0; w < 8; w++) { ts += red[w]; tss += red[w + 8]; }
        const float mean = ts * (1.0f / UNITS);
        red[0] = mean;
        red[1] = rsqrtf(tss * (1.0f / UNITS) - mean * mean + LN_EPS);
    }
    __syncthreads();
    const float mean = red[0], rstd = red[1];

    const float4 g = ((const float4*)gamma)[tid];
    const float4 bb = ((const float4*)beta)[tid];
    __half2* oh = (__half2*)(g_h + (size_t)row * UNITS);
    oh[2*tid]   = __floats2half2_rn((x.x - mean) * rstd * g.x + bb.x,
                                    (x.y - mean) * rstd * g.y + bb.y);
    oh[2*tid+1] = __floats2half2_rn((x.z - mean) * rstd * g.z + bb.z,
                                    (x.w - mean) * rstd * g.w + bb.w);
}

// LN2: h2 = LN(hm); memory rows -> g_h2, output row (m==8) -> out directly
__global__ void __launch_bounds__(256)
ln2_kernel(const float* __restrict__ gamma, const float* __restrict__ beta,
           float* __restrict__ out)
{
    const int row = blockIdx.x;
    const int tid = threadIdx.x;
    const float4 x = ((const float4*)(g_hm + (size_t)row * UNITS))[tid];

    float s  = x.x + x.y + x.z + x.w;
    float ss = x.x*x.x + x.y*x.y + x.z*x.z + x.w*x.w;
    __shared__ float red[16];
    #pragma unroll
    for (int o = 16; o > 0; o >>= 1) {
        s  += __shfl_down_sync(0xffffffff, s, o);
        ss += __shfl_down_sync(0xffffffff, ss, o);
    }
    const int warp = tid >> 5, lane = tid & 31;
    if (lane == 0) { red[warp] = s; red[warp + 8] = ss; }
    __syncthreads();
    if (tid == 0) {
        float ts = 0.0f, tss = 0.0f;
        #pragma unroll
        for (int w = 0; w < 8; w++) { ts += red[w]; tss += red[w + 8]; }
        const float mean = ts * (1.0f / UNITS);
        red[0] = mean;
        red[1] = rsqrtf(tss * (1.0f / UNITS) - mean * mean + LN_EPS);
    }
    __syncthreads();
    const float mean = red[0], rstd = red[1];

    const float4 g = ((const float4*)gamma)[tid];
    const float4 bb = ((const float4*)beta)[tid];
    float4 o;
    o.x = (x.x - mean) * rstd * g.x + bb.x;
    o.y = (x.y - mean) * rstd * g.y + bb.y;
    o.z = (x.z - mean) * rstd * g.z + bb.z;
    o.w = (x.w - mean) * rstd * g.w + bb.w;

    const int b = row / SLOTS, m = row - b * SLOTS;
    float* dst = (m == MEMS) ? (out + (size_t)b * UNITS)
                             : (g_h2 + (size_t)row * UNITS);
    ((float4*)dst)[tid] = o;
}

// ---------------- host launcher ---------------------------------------------
extern "C" void kernel_launch(void* const* d_in, const int* in_sizes, int n_in,
                              void* d_out, int out_size)
{
    const float* inputs           = (const float*)d_in[0];
    const float* state            = (const float*)d_in[1];
    const float* input_kernel     = (const float*)d_in[2];
    const float* input_bias_w     = (const float*)d_in[3];
    const float* gate_kernel      = (const float*)d_in[4];
    const float* recurrent_kernel = (const float*)d_in[5];
    const float* recurrent_bias   = (const float*)d_in[6];
    const float* attention_kernel = (const float*)d_in[7];
    const float* attention_bias   = (const float*)d_in[8];
    const float* mlp_kernel       = (const float*)d_in[9];
    const float* mlp_bias         = (const float*)d_in[10];
    const float* ln_gamma         = (const float*)d_in[11];
    const float* ln_beta          = (const float*)d_in[12];
    const float* rel_kernel       = (const float*)d_in[13];
    float* out = (float*)d_out;

    static __half *p_memplus = nullptr, *p_qkv, *p_h, *p_t, *p_xr,
                  *p_wtig, *p_wtrec, *p_wtatt, *p_wtmlp;
    static float *p_hm, *p_h2, *p_g0;
    static bool init_done = false;
    if (!init_done) {
        cudaGetSymbolAddress((void**)&p_memplus, g_memplus);
        cudaGetSymbolAddress((void**)&p_qkv, g_qkv);
        cudaGetSymbolAddress((void**)&p_h, g_h);
        cudaGetSymbolAddress((void**)&p_t, g_t);
        cudaGetSymbolAddress((void**)&p_xr, g_xr);
        cudaGetSymbolAddress((void**)&p_wtig, wt_ingate);
        cudaGetSymbolAddress((void**)&p_wtrec, wt_rec);
        cudaGetSymbolAddress((void**)&p_wtatt, wt_att);
        cudaGetSymbolAddress((void**)&p_wtmlp, wt_mlp);
        cudaGetSymbolAddress((void**)&p_hm, g_hm);
        cudaGetSymbolAddress((void**)&p_h2, g_h2);
        cudaGetSymbolAddress((void**)&p_g0, g_g0);

        cudaFuncSetAttribute(hgemm<EPI_BIAS_H, false>, cudaFuncAttributeMaxDynamicSharedMemorySize, HG_SMEM);
        cudaFuncSetAttribute(hgemm<EPI_GELU,   false>, cudaFuncAttributeMaxDynamicSharedMemorySize, HG_SMEM);
        cudaFuncSetAttribute(hgemm<EPI_RES,    false>, cudaFuncAttributeMaxDynamicSharedMemorySize, HG_SMEM);
        cudaFuncSetAttribute(hgemm<EPI_INGATE, false>, cudaFuncAttributeMaxDynamicSharedMemorySize, HG_SMEM);
        cudaFuncSetAttribute(hgemm<EPI_GATES,  true >, cudaFuncAttributeMaxDynamicSharedMemorySize, HG_SMEM);
        init_done = true;
    }

    // 1) inputs -> fp16
    to_half_kernel<<<(BATCH*DIMD/4 + 255)/256, 256>>>(inputs, p_xr, BATCH*DIMD/4);
    // 2) all weight transposes (one launch)
    transpose_all_kernel<<<dim3(320, 32), dim3(32, 8)>>>(
        input_kernel, gate_kernel, recurrent_kernel, attention_kernel, mlp_kernel);
    // 3) state -> memplus slots 0..7
    copy_state_kernel<<<GROWS, 256>>>(state);
    // 4) fused input+gate GEMM: [2048 x 3072] ; cols<1024 -> memplus slot8, cols>=1024 -> g0
    hgemm<EPI_INGATE, false><<<dim3(3*UNITS/BN, BATCH/BM), 512, HG_SMEM>>>(
        p_xr, DIMD, p_wtig, DIMD, input_bias_w,
        nullptr, 0, nullptr, nullptr, p_g0,
        p_memplus + (size_t)MEMS * UNITS, SLOTS * UNITS,
        BATCH, 3 * UNITS, DIMD);
    // 5) rel-pos table
    tab_kernel<<<17, 256>>>();
    // 6) qkv GEMM  (profiled launch)
    hgemm<EPI_BIAS_H, false><<<dim3(3*UNITS/BN, ROWS/BM), 512, HG_SMEM>>>(
        p_memplus, UNITS, p_wtatt, UNITS, attention_bias,
        nullptr, 0, nullptr, nullptr, nullptr,
        p_qkv, 3 * UNITS, ROWS, 3 * UNITS, UNITS);
    // 7) rel emb
    relgemm_kernel<<<dim3(UNITS / 256, 17), 256>>>(rel_kernel);
    // 8) attention
    attn_kernel<<<dim3(BATCH, HEADS), 64>>>();
    // 9) LN1
    ln1_kernel<<<ROWS, 256>>>(ln_gamma, ln_beta);
    // 10) MLP1
    hgemm<EPI_GELU, false><<<dim3(UNITS/BN, ROWS/BM), 512, HG_SMEM>>>(
        p_h, UNITS, p_wtmlp, UNITS, mlp_bias,
        nullptr, 0, nullptr, nullptr, nullptr,
        p_t, UNITS, ROWS, UNITS, UNITS);
    // 11) MLP2 (+residual h)
    hgemm<EPI_RES, false><<<dim3(UNITS/BN, ROWS/BM), 512, HG_SMEM>>>(
        p_t, UNITS, p_wtmlp + (size_t)UNITS * UNITS, UNITS, mlp_bias + UNITS,
        p_h, UNITS, nullptr, nullptr, nullptr,
        p_hm, UNITS, ROWS, UNITS, UNITS);
    // 12) LN2 (memory rows -> h2, output row -> out)
    ln2_kernel<<<ROWS, 256>>>(ln_gamma + UNITS, ln_beta + UNITS, out);
    // 13) recurrent-gates GEMM with full gate epilogue -> out[B*U ...]
    hgemm<EPI_GATES, true><<<dim3(2*UNITS/BN, GROWS/BM), 512, HG_SMEM>>>(
        p_memplus, UNITS, p_wtrec, UNITS, recurrent_bias,
        nullptr, 0, p_g0, state, p_h2,
        out + (size_t)BATCH * UNITS, UNITS,
        GROWS, 2 * UNITS, UNITS);
}